// round 1
// baseline (speedup 1.0000x reference)
#include <cuda_runtime.h>
#include <math.h>

#define N_SAMPLES 131072
#define N_EVENTS 128
#define N_ATOMS 32
#define ATOM_SIZE 512
#define LATENT 16
#define TIME_DIM 17
#define LAYERS 7

// ---------------- device scratch (no allocation allowed) ----------------
__device__ float g_x[2][N_EVENTS][LATENT];
__device__ float g_t[2][N_EVENTS][TIME_DIM * 2];
__device__ float g_coef[N_EVENTS][N_ATOMS];
__device__ float g_amp[N_EVENTS];
__device__ int   g_pos[N_EVENTS];
__device__ float g_wav[N_EVENTS][ATOM_SIZE];

// ---------------- kernel 1: tree expansion + heads ----------------
// One block. 7 layers of event doubling; each layer is two tiny matmuls.
__global__ void tree_kernel(const float* __restrict__ base_latent,
                            const float* __restrict__ to_time_W,
                            const float* __restrict__ split_W,
                            const float* __restrict__ split_b,
                            const float* __restrict__ to_atoms_W,
                            const float* __restrict__ to_atoms_b,
                            const float* __restrict__ to_amp_W,
                            const float* __restrict__ to_amp_b) {
    const int tid = threadIdx.x;

    if (tid < LATENT)       g_x[0][0][tid] = base_latent[tid];
    if (tid < TIME_DIM * 2) g_t[0][0][tid] = 0.0f;
    __syncthreads();

    for (int i = 0; i < LAYERS; i++) {
        const int e = 1 << i;
        const int ping = i & 1, pong = ping ^ 1;
        const float* Wt = to_time_W + i * 68 * LATENT;  // (68,16)
        const float* Ws = split_W   + i * 32 * LATENT;  // (32,16)
        const float* bs = split_b   + i * 32;

        // time offsets: e parents x 68 outputs; o = c*34 + t*2 + s
        for (int idx = tid; idx < e * 68; idx += blockDim.x) {
            const int p = idx / 68, o = idx % 68;
            const float* xp = g_x[ping][p];
            const float* w  = Wt + o * LATENT;
            float acc = 0.0f;
#pragma unroll
            for (int k = 0; k < LATENT; k++) acc += xp[k] * w[k];
            const int c = o / 34, r = o % 34;
            g_t[pong][2 * p + c][r] = g_t[ping][p][r] + acc;
        }
        // split latents: e parents x 32 outputs -> child latents
        for (int idx = tid; idx < e * 32; idx += blockDim.x) {
            const int p = idx / 32, o = idx % 32;
            const float* xp = g_x[ping][p];
            const float* w  = Ws + o * LATENT;
            float acc = bs[o];
#pragma unroll
            for (int k = 0; k < LATENT; k++) acc += xp[k] * w[k];
            g_x[pong][2 * p + (o >> 4)][o & 15] = acc;
        }
        __syncthreads();
    }

    const int F = LAYERS & 1;  // final buffer = 1

    // dirac positions (argmax one-hot products collapse to a binary number,
    // bit 0 = MSB) + amplitude head
    if (tid < N_EVENTS) {
        int pos = 0;
#pragma unroll
        for (int t = 0; t < TIME_DIM; t++) {
            const int bit = (g_t[F][tid][2 * t + 1] > g_t[F][tid][2 * t]) ? 1 : 0;
            pos |= bit << (TIME_DIM - 1 - t);
        }
        g_pos[tid] = pos;

        float a = to_amp_b[0];
#pragma unroll
        for (int k = 0; k < LATENT; k++) a += g_x[F][tid][k] * to_amp_W[k];
        g_amp[tid] = a;
    }

    // atom coefficients: 128 x 32
    for (int idx = tid; idx < N_EVENTS * N_ATOMS; idx += blockDim.x) {
        const int ev = idx / N_ATOMS, o = idx % N_ATOMS;
        float acc = to_atoms_b[o];
        const float* w = to_atoms_W + o * LATENT;
#pragma unroll
        for (int k = 0; k < LATENT; k++) acc += g_x[F][ev][k] * w[k];
        g_coef[ev][o] = acc;
    }
}

// ---------------- kernel 2: per-event waveform + norm + amp ----------------
// 128 blocks (one per event), 512 threads (one per sample).
__global__ void wav_kernel(const float* __restrict__ atoms) {
    const int e = blockIdx.x;
    const int j = threadIdx.x;

    __shared__ float sc[N_ATOMS];
    __shared__ float red[16];
    __shared__ float s_scale;

    if (j < N_ATOMS) sc[j] = g_coef[e][j];
    __syncthreads();

    float w = 0.0f;
#pragma unroll
    for (int k = 0; k < N_ATOMS; k++) w += sc[k] * atoms[k * ATOM_SIZE + j];

    const float win = 0.54f - 0.46f * cosf(6.283185307179586f * (float)j * (1.0f / (float)ATOM_SIZE));
    w *= win;

    // block reduce sum of squares (16 warps)
    float ss = w * w;
#pragma unroll
    for (int off = 16; off; off >>= 1) ss += __shfl_down_sync(0xffffffffu, ss, off);
    if ((j & 31) == 0) red[j >> 5] = ss;
    __syncthreads();
    if (j < 32) {
        float v = (j < 16) ? red[j] : 0.0f;
#pragma unroll
        for (int off = 8; off; off >>= 1) v += __shfl_down_sync(0xffffffffu, v, off);
        if (j == 0) s_scale = g_amp[e] / (sqrtf(v) + 1e-8f);
    }
    __syncthreads();

    g_wav[e][j] = w * s_scale;
}

// ---------------- kernel 3: deterministic gather into output ----------------
// Each output sample scans the 128 events; a window hits at most a handful of
// blocks so almost all iterations are cheap compares.
__global__ void gather_kernel(float* __restrict__ out) {
    __shared__ int sp[N_EVENTS];
    const int tid = threadIdx.x;
    if (tid < N_EVENTS) sp[tid] = g_pos[tid];
    __syncthreads();

    const int t = blockIdx.x * blockDim.x + tid;
    float acc = 0.0f;
#pragma unroll 4
    for (int e = 0; e < N_EVENTS; e++) {
        const unsigned d = (unsigned)(t - sp[e]);
        if (d < (unsigned)ATOM_SIZE) acc += g_wav[e][d];
    }
    out[t] = acc;
}

// ---------------- launch ----------------
extern "C" void kernel_launch(void* const* d_in, const int* in_sizes, int n_in,
                              void* d_out, int out_size) {
    const float* base_latent = (const float*)d_in[0];
    const float* to_time_W   = (const float*)d_in[1];
    const float* split_W     = (const float*)d_in[2];
    const float* split_b     = (const float*)d_in[3];
    const float* atoms       = (const float*)d_in[4];
    const float* to_atoms_W  = (const float*)d_in[5];
    const float* to_atoms_b  = (const float*)d_in[6];
    const float* to_amp_W    = (const float*)d_in[7];
    const float* to_amp_b    = (const float*)d_in[8];
    float* out = (float*)d_out;

    tree_kernel<<<1, 256>>>(base_latent, to_time_W, split_W, split_b,
                            to_atoms_W, to_atoms_b, to_amp_W, to_amp_b);
    wav_kernel<<<N_EVENTS, ATOM_SIZE>>>(atoms);
    gather_kernel<<<N_SAMPLES / 256, 256>>>(out);
}

// round 3
// speedup vs baseline: 1.7837x; 1.7837x over previous
#include <cuda_runtime.h>
#include <math.h>

#define N_SAMPLES 131072
#define N_EVENTS 128
#define N_ATOMS 32
#define ATOM_SIZE 512
#define LATENT 16
#define TIME_DIM 17
#define LAYERS 7

// ---------------- device scratch (no allocation allowed) ----------------
__device__ float g_coef[N_EVENTS][N_ATOMS];
__device__ float g_amp[N_EVENTS];
__device__ int   g_pos[N_EVENTS];
__device__ float g_wav[N_EVENTS][ATOM_SIZE];

// ---------------- kernel 1: tree expansion + heads (all in shared) ----------
// One block, 256 threads. State ping-pongs in shared memory; per-layer weights
// staged into shared. Times are carried as 17 per-event DIFFS (odd-even),
// since only the sign of each diff determines the dirac bit.
__global__ void tree_kernel(const float* __restrict__ base_latent,
                            const float* __restrict__ to_time_W,
                            const float* __restrict__ split_W,
                            const float* __restrict__ split_b,
                            const float* __restrict__ to_atoms_W,
                            const float* __restrict__ to_atoms_b,
                            const float* __restrict__ to_amp_W,
                            const float* __restrict__ to_amp_b) {
    __shared__ float sx[2][N_EVENTS][LATENT];      // latents ping-pong
    __shared__ float sd[2][N_EVENTS][TIME_DIM];    // time-diff ping-pong
    __shared__ float sWtd[2 * TIME_DIM][LATENT];   // (W_odd - W_even) rows, c*17+t
    __shared__ float sWs[2 * LATENT][LATENT];      // split weights (32,16)
    __shared__ float sbs[2 * LATENT];              // split bias

    const int tid = threadIdx.x;

    if (tid < LATENT)   sx[0][0][tid] = base_latent[tid];
    if (tid < TIME_DIM) sd[0][0][tid] = 0.0f;

    for (int i = 0; i < LAYERS; i++) {
        const int e = 1 << i;
        const int ping = i & 1, pong = ping ^ 1;
        const float* Wt = to_time_W + i * (2 * TIME_DIM * 2) * LATENT; // (68,16)
        const float* Ws = split_W   + i * (2 * LATENT) * LATENT;       // (32,16)
        const float* bs = split_b   + i * (2 * LATENT);

        // stage this layer's weights: diff rows for time head, split W/b
        for (int idx = tid; idx < 2 * TIME_DIM * LATENT; idx += blockDim.x) {
            const int rd = idx / LATENT, k = idx % LATENT;
            const int c = rd / TIME_DIM, t = rd % TIME_DIM;
            const int ro = c * (2 * TIME_DIM) + 2 * t;   // even row in orig
            sWtd[rd][k] = Wt[(ro + 1) * LATENT + k] - Wt[ro * LATENT + k];
        }
        for (int idx = tid; idx < 2 * LATENT * LATENT; idx += blockDim.x)
            sWs[idx / LATENT][idx % LATENT] = Ws[idx];
        if (tid < 2 * LATENT) sbs[tid] = bs[tid];
        __syncthreads();

        // time diffs: e parents x 34 outputs (17 per child)
        for (int idx = tid; idx < e * 2 * TIME_DIM; idx += blockDim.x) {
            const int p = idx / (2 * TIME_DIM), o = idx % (2 * TIME_DIM);
            const int c = o / TIME_DIM, t = o % TIME_DIM;
            const float* xp = sx[ping][p];
            const float* w  = sWtd[o];
            float acc = 0.0f;
#pragma unroll
            for (int k = 0; k < LATENT; k++) acc += xp[k] * w[k];
            sd[pong][2 * p + c][t] = sd[ping][p][t] + acc;
        }
        // split latents: e parents x 32 outputs -> child latents
        for (int idx = tid; idx < e * 2 * LATENT; idx += blockDim.x) {
            const int p = idx / (2 * LATENT), o = idx % (2 * LATENT);
            const float* xp = sx[ping][p];
            const float* w  = sWs[o];
            float acc = sbs[o];
#pragma unroll
            for (int k = 0; k < LATENT; k++) acc += xp[k] * w[k];
            sx[pong][2 * p + (o >> 4)][o & (LATENT - 1)] = acc;
        }
        __syncthreads();
    }

    const int F = LAYERS & 1;  // final buffer = 1

    // dirac position (bit t = sign of diff, MSB first) + amplitude head
    if (tid < N_EVENTS) {
        int pos = 0;
#pragma unroll
        for (int t = 0; t < TIME_DIM; t++) {
            const int bit = (sd[F][tid][t] > 0.0f) ? 1 : 0;
            pos |= bit << (TIME_DIM - 1 - t);
        }
        g_pos[tid] = pos;

        float a = to_amp_b[0];
#pragma unroll
        for (int k = 0; k < LATENT; k++) a += sx[F][tid][k] * to_amp_W[k];
        g_amp[tid] = a;
    }

    // atom coefficients: 128 x 32
    for (int idx = tid; idx < N_EVENTS * N_ATOMS; idx += blockDim.x) {
        const int ev = idx / N_ATOMS, o = idx % N_ATOMS;
        float acc = to_atoms_b[o];
        const float* w = to_atoms_W + o * LATENT;
#pragma unroll
        for (int k = 0; k < LATENT; k++) acc += sx[F][ev][k] * w[k];
        g_coef[ev][o] = acc;
    }
}

// ---------------- kernel 2: per-event waveform + norm + amp ----------------
// 128 blocks (one per event), 512 threads (one per sample).
__global__ void wav_kernel(const float* __restrict__ atoms) {
    const int e = blockIdx.x;
    const int j = threadIdx.x;

    __shared__ float sc[N_ATOMS];
    __shared__ float red[16];
    __shared__ float s_scale;

    if (j < N_ATOMS) sc[j] = g_coef[e][j];
    __syncthreads();

    float w = 0.0f;
#pragma unroll
    for (int k = 0; k < N_ATOMS; k++) w += sc[k] * atoms[k * ATOM_SIZE + j];

    const float win = 0.54f - 0.46f * cosf(6.283185307179586f * (float)j * (1.0f / (float)ATOM_SIZE));
    w *= win;

    // block reduce sum of squares (16 warps)
    float ss = w * w;
#pragma unroll
    for (int off = 16; off; off >>= 1) ss += __shfl_down_sync(0xffffffffu, ss, off);
    if ((j & 31) == 0) red[j >> 5] = ss;
    __syncthreads();
    if (j < 32) {
        float v = (j < 16) ? red[j] : 0.0f;
#pragma unroll
        for (int off = 8; off; off >>= 1) v += __shfl_down_sync(0xffffffffu, v, off);
        if (j == 0) s_scale = g_amp[e] / (sqrtf(v) + 1e-8f);
    }
    __syncthreads();

    g_wav[e][j] = w * s_scale;
}

// ---------------- kernel 3: deterministic gather into output ----------------
__global__ void gather_kernel(float* __restrict__ out) {
    __shared__ int sp[N_EVENTS];
    const int tid = threadIdx.x;
    if (tid < N_EVENTS) sp[tid] = g_pos[tid];
    __syncthreads();

    const int t = blockIdx.x * blockDim.x + tid;
    float acc = 0.0f;
#pragma unroll 4
    for (int e = 0; e < N_EVENTS; e++) {
        const unsigned d = (unsigned)(t - sp[e]);
        if (d < (unsigned)ATOM_SIZE) acc += g_wav[e][d];
    }
    out[t] = acc;
}

// ---------------- launch ----------------
extern "C" void kernel_launch(void* const* d_in, const int* in_sizes, int n_in,
                              void* d_out, int out_size) {
    const float* base_latent = (const float*)d_in[0];
    const float* to_time_W   = (const float*)d_in[1];
    const float* split_W     = (const float*)d_in[2];
    const float* split_b     = (const float*)d_in[3];
    const float* atoms       = (const float*)d_in[4];
    const float* to_atoms_W  = (const float*)d_in[5];
    const float* to_atoms_b  = (const float*)d_in[6];
    const float* to_amp_W    = (const float*)d_in[7];
    const float* to_amp_b    = (const float*)d_in[8];
    float* out = (float*)d_out;

    tree_kernel<<<1, 256>>>(base_latent, to_time_W, split_W, split_b,
                            to_atoms_W, to_atoms_b, to_amp_W, to_amp_b);
    wav_kernel<<<N_EVENTS, ATOM_SIZE>>>(atoms);
    gather_kernel<<<N_SAMPLES / 256, 256>>>(out);
}